// round 2
// baseline (speedup 1.0000x reference)
#include <cuda_runtime.h>
#include <cuda_bf16.h>
#include <cstdint>

// ---------------------------------------------------------------------------
// Problem dims
// ---------------------------------------------------------------------------
#define BATCH   16
#define SEQ     256
#define EMBED   512
#define HIDDEN  1024
#define GATES   (4 * HIDDEN)        // 4096
#define VOCAB   32000
#define MROWS   (BATCH * SEQ)       // 4096
#define NBLK    128                 // persistent LSTM grid size

// ---------------------------------------------------------------------------
// Scratch (device globals; no runtime allocation allowed)
// ---------------------------------------------------------------------------
__device__ float g_xemb  [MROWS * EMBED];     //  8 MB
__device__ float g_gatesx[MROWS * GATES];     // 64 MB: input-projection preacts (+biases)
__device__ float g_hs0   [MROWS * HIDDEN];    // 16 MB
__device__ float g_hs1   [MROWS * HIDDEN];    // 16 MB
__device__ float g_hbuf  [2][BATCH * HIDDEN]; // ping-pong h state
__device__ unsigned g_cnt;                    // grid barrier counter
__device__ volatile unsigned g_gen;           // grid barrier generation (monotonic)

// ---------------------------------------------------------------------------
// Packed f32x2 helpers (FFMA2 — 2x fp32 FMA throughput; PTX-only)
// ---------------------------------------------------------------------------
__device__ __forceinline__ void ffma2(unsigned long long& d,
                                      unsigned long long a,
                                      unsigned long long b) {
    asm("fma.rn.f32x2 %0, %1, %2, %0;" : "+l"(d) : "l"(a), "l"(b));
}
__device__ __forceinline__ unsigned long long pack2(float v) {
    unsigned long long r;
    unsigned int u = __float_as_uint(v);
    asm("mov.b64 %0, {%1, %1};" : "=l"(r) : "r"(u));
    return r;
}
__device__ __forceinline__ float2 unpack2(unsigned long long v) {
    unsigned int lo, hi;
    asm("mov.b64 {%0, %1}, %2;" : "=r"(lo), "=r"(hi) : "l"(v));
    return make_float2(__uint_as_float(lo), __uint_as_float(hi));
}

// ---------------------------------------------------------------------------
// Grid-wide barrier (sense via monotonically increasing generation).
// All NBLK blocks are guaranteed co-resident (NBLK <= SM count, tiny regs).
// ---------------------------------------------------------------------------
__device__ __forceinline__ void grid_bar(unsigned target) {
    __threadfence();
    __syncthreads();
    if (threadIdx.x == 0) {
        unsigned arr = atomicAdd(&g_cnt, 1u);
        if (arr == NBLK - 1) {
            g_cnt = 0;
            __threadfence();
            g_gen = target;            // release
        } else {
            while ((int)(g_gen - target) < 0) {}
            __threadfence();
        }
    }
    __syncthreads();
}

// ---------------------------------------------------------------------------
// Embedding gather (float4 rows)
// ---------------------------------------------------------------------------
__global__ void embed_kernel(const int* __restrict__ x,
                             const float* __restrict__ emb,
                             float* __restrict__ out) {
    int idx = blockIdx.x * 256 + threadIdx.x;   // over float4 units
    int row = idx >> 7;                         // EMBED/4 = 128 per row
    int e4  = idx & 127;
    const float4* src = (const float4*)(emb + ((size_t)x[row] << 9));
    ((float4*)out)[idx] = src[e4];
}

// ---------------------------------------------------------------------------
// fp32 GEMM:  C[M,N] = A[M,K] @ W[N,K]^T + b1 (+ b2)
// 128x128x16 tile, 256 threads, 16(m as 8 f32x2-pairs) x 4(n) micro-tile.
// Requires M%128==0, N%128==0, K%16==0.
// ---------------------------------------------------------------------------
__global__ __launch_bounds__(256, 2)
void gemm_abT(const float* __restrict__ A, const float* __restrict__ W,
              const float* __restrict__ b1, const float* __restrict__ b2,
              float* __restrict__ C, int M, int N, int K) {
    __shared__ float As[16][132];
    __shared__ float Ws[16][132];

    int tid = threadIdx.x;
    int m0 = blockIdx.y << 7;
    int n0 = blockIdx.x << 7;
    int lr = tid >> 2;              // 0..63
    int lc = (tid & 3) << 2;        // 0,4,8,12
    int ty = tid >> 5;              // 0..7  -> 16 rows
    int tx = tid & 31;              // 0..31 -> 4 cols

    unsigned long long acc[4][8];
#pragma unroll
    for (int j = 0; j < 4; j++)
#pragma unroll
        for (int i = 0; i < 8; i++) acc[j][i] = 0ull;

    const float* Ar0 = A + (size_t)(m0 + lr) * K;
    const float* Ar1 = A + (size_t)(m0 + lr + 64) * K;
    const float* Wr0 = W + (size_t)(n0 + lr) * K;
    const float* Wr1 = W + (size_t)(n0 + lr + 64) * K;

    for (int k0 = 0; k0 < K; k0 += 16) {
        float4 a0 = *(const float4*)(Ar0 + k0 + lc);
        float4 a1 = *(const float4*)(Ar1 + k0 + lc);
        float4 w0 = *(const float4*)(Wr0 + k0 + lc);
        float4 w1 = *(const float4*)(Wr1 + k0 + lc);
        __syncthreads();
        As[lc+0][lr] = a0.x; As[lc+1][lr] = a0.y; As[lc+2][lr] = a0.z; As[lc+3][lr] = a0.w;
        As[lc+0][lr+64] = a1.x; As[lc+1][lr+64] = a1.y; As[lc+2][lr+64] = a1.z; As[lc+3][lr+64] = a1.w;
        Ws[lc+0][lr] = w0.x; Ws[lc+1][lr] = w0.y; Ws[lc+2][lr] = w0.z; Ws[lc+3][lr] = w0.w;
        Ws[lc+0][lr+64] = w1.x; Ws[lc+1][lr+64] = w1.y; Ws[lc+2][lr+64] = w1.z; Ws[lc+3][lr+64] = w1.w;
        __syncthreads();

#pragma unroll
        for (int kk = 0; kk < 16; kk++) {
            ulonglong2 ap01 = *(const ulonglong2*)&As[kk][ty*16 + 0];
            ulonglong2 ap23 = *(const ulonglong2*)&As[kk][ty*16 + 4];
            ulonglong2 ap45 = *(const ulonglong2*)&As[kk][ty*16 + 8];
            ulonglong2 ap67 = *(const ulonglong2*)&As[kk][ty*16 + 12];
            float4 wv = *(const float4*)&Ws[kk][tx*4];
            unsigned long long wp0 = pack2(wv.x), wp1 = pack2(wv.y);
            unsigned long long wp2 = pack2(wv.z), wp3 = pack2(wv.w);
            unsigned long long ap[8] = {ap01.x, ap01.y, ap23.x, ap23.y,
                                        ap45.x, ap45.y, ap67.x, ap67.y};
#pragma unroll
            for (int i = 0; i < 8; i++) {
                ffma2(acc[0][i], wp0, ap[i]);
                ffma2(acc[1][i], wp1, ap[i]);
                ffma2(acc[2][i], wp2, ap[i]);
                ffma2(acc[3][i], wp3, ap[i]);
            }
        }
    }

    int n = n0 + (tx << 2);
    float4 bv = *(const float4*)(b1 + n);
    if (b2) {
        float4 t2 = *(const float4*)(b2 + n);
        bv.x += t2.x; bv.y += t2.y; bv.z += t2.z; bv.w += t2.w;
    }
#pragma unroll
    for (int i = 0; i < 8; i++) {
        float2 c0f = unpack2(acc[0][i]);
        float2 c1f = unpack2(acc[1][i]);
        float2 c2f = unpack2(acc[2][i]);
        float2 c3f = unpack2(acc[3][i]);
        int r0 = m0 + ty*16 + 2*i;
        float4 o0 = make_float4(c0f.x + bv.x, c1f.x + bv.y, c2f.x + bv.z, c3f.x + bv.w);
        float4 o1 = make_float4(c0f.y + bv.x, c1f.y + bv.y, c2f.y + bv.z, c3f.y + bv.w);
        *(float4*)(C + (size_t)r0 * N + n) = o0;
        *(float4*)(C + (size_t)(r0 + 1) * N + n) = o1;
    }
}

// ---------------------------------------------------------------------------
// Persistent LSTM layer: 128 blocks x 256 threads, whole sequence in one
// launch. Each block owns 8 hidden columns (x4 gates = 32 W_hh rows); each
// thread = 1 row x 1 batch-pair. h ping-pongs in global (read via __ldcg:
// L1 is not coherent across SMs); c lives in SMEM for the whole layer.
// One grid barrier per timestep.
// ---------------------------------------------------------------------------
__global__ __launch_bounds__(256)
void lstm_layer(const float* __restrict__ Whh,
                const float* __restrict__ gatesx,
                const float* __restrict__ h0l, const float* __restrict__ c0l,
                float* __restrict__ hs,
                float* __restrict__ hT, float* __restrict__ cT) {
    __shared__ float h_sm[512][18];
    __shared__ float gate_sm[32][17];
    __shared__ float c_sm[128];
    __shared__ unsigned base_sh;

    int tid = threadIdx.x;
    int bid = blockIdx.x;

    if (tid == 0) base_sh = g_gen;   // stable: only changes after all blocks arrive
    __syncthreads();
    unsigned tgt = base_sh;

    // init state
    if (tid < 128) {
        g_hbuf[0][bid * 128 + tid] = h0l[bid * 128 + tid];
        int b = tid >> 3, cc = tid & 7;
        c_sm[tid] = c0l[b * HIDDEN + bid * 8 + cc];
    }
    grid_bar(++tgt);

    int lrow = tid >> 3;             // 0..31
    int pr2  = (tid & 7) << 1;       // batch-pair offset
    int q    = lrow >> 3;            // gate index 0..3
    int col  = bid * 8 + (lrow & 7); // hidden column
    const float* wr_base = Whh + (size_t)(q * HIDDEN + col) * HIDDEN;

    for (int t = 0; t < SEQ; t++) {
        const float* hin  = g_hbuf[t & 1];
        float*       hout = g_hbuf[(t + 1) & 1];
        unsigned long long acc = 0ull;

#pragma unroll
        for (int kc = 0; kc < 2; kc++) {
            __syncthreads();
            // load h chunk [512 k x 16 b] transposed into SMEM (L2-fresh)
            for (int i = tid; i < 2048; i += 256) {
                int b  = i >> 7;
                int k4 = (i & 127) << 2;
                float4 v = __ldcg((const float4*)(hin + b * HIDDEN + kc * 512 + k4));
                h_sm[k4 + 0][b] = v.x; h_sm[k4 + 1][b] = v.y;
                h_sm[k4 + 2][b] = v.z; h_sm[k4 + 3][b] = v.w;
            }
            __syncthreads();
            const float* wr = wr_base + kc * 512;
#pragma unroll 4
            for (int k = 0; k < 512; k += 4) {
                float4 w = *(const float4*)(wr + k);
                ffma2(acc, pack2(w.x), *(const unsigned long long*)&h_sm[k + 0][pr2]);
                ffma2(acc, pack2(w.y), *(const unsigned long long*)&h_sm[k + 1][pr2]);
                ffma2(acc, pack2(w.z), *(const unsigned long long*)&h_sm[k + 2][pr2]);
                ffma2(acc, pack2(w.w), *(const unsigned long long*)&h_sm[k + 3][pr2]);
            }
        }

        float2 u = unpack2(acc);
        gate_sm[lrow][pr2]     = u.x;
        gate_sm[lrow][pr2 + 1] = u.y;
        __syncthreads();

        if (tid < 128) {
            int b = tid >> 3, cc = tid & 7;
            int colp = bid * 8 + cc;
            size_t gb = (size_t)(b * SEQ + t) * GATES;
            float gi = gate_sm[cc][b]      + gatesx[gb + colp];
            float gf = gate_sm[8 + cc][b]  + gatesx[gb + 1024 + colp];
            float gg = gate_sm[16 + cc][b] + gatesx[gb + 2048 + colp];
            float go = gate_sm[24 + cc][b] + gatesx[gb + 3072 + colp];
            float si = 1.f / (1.f + expf(-gi));
            float sf = 1.f / (1.f + expf(-gf));
            float tg = tanhf(gg);
            float so = 1.f / (1.f + expf(-go));
            float cn = sf * c_sm[tid] + si * tg;
            c_sm[tid] = cn;
            float hn = so * tanhf(cn);
            hout[b * HIDDEN + colp] = hn;
            hs[(size_t)(b * SEQ + t) * HIDDEN + colp] = hn;
        }
        grid_bar(++tgt);
    }

    // final state writeout (SEQ even -> final h in buffer 0)
    if (tid < 128) {
        hT[bid * 128 + tid] = __ldcg(&g_hbuf[0][bid * 128 + tid]);
        int b = tid >> 3;
        cT[b * HIDDEN + bid * 8 + (tid & 7)] = c_sm[tid];
    }
}

// ---------------------------------------------------------------------------
// Launch: 6 graph nodes total (keeps graph upload device-alloc at zero)
// ---------------------------------------------------------------------------
extern "C" void kernel_launch(void* const* d_in, const int* in_sizes, int n_in,
                              void* d_out, int out_size) {
    const int*   x     = (const int*)  d_in[0];
    const float* h0    = (const float*)d_in[1];
    const float* c0    = (const float*)d_in[2];
    const float* emb   = (const float*)d_in[3];
    const float* W_ih0 = (const float*)d_in[4];
    const float* W_hh0 = (const float*)d_in[5];
    const float* b_ih0 = (const float*)d_in[6];
    const float* b_hh0 = (const float*)d_in[7];
    const float* W_ih1 = (const float*)d_in[8];
    const float* W_hh1 = (const float*)d_in[9];
    const float* b_ih1 = (const float*)d_in[10];
    const float* b_hh1 = (const float*)d_in[11];
    const float* fc_W  = (const float*)d_in[12];
    const float* fc_b  = (const float*)d_in[13];

    float* out    = (float*)d_out;
    float* logits = out;
    float* hT     = out + (size_t)MROWS * VOCAB;
    float* cT     = hT + 2 * BATCH * HIDDEN;

    float *p_xemb, *p_gatesx, *p_hs0, *p_hs1;
    cudaGetSymbolAddress((void**)&p_xemb,   g_xemb);
    cudaGetSymbolAddress((void**)&p_gatesx, g_gatesx);
    cudaGetSymbolAddress((void**)&p_hs0,    g_hs0);
    cudaGetSymbolAddress((void**)&p_hs1,    g_hs1);

    const int SH = BATCH * HIDDEN;

    // 1) embedding
    embed_kernel<<<(MROWS * (EMBED / 4)) / 256, 256>>>(x, emb, p_xemb);

    // 2) layer-0 input projection (both biases folded in)
    gemm_abT<<<dim3(GATES / 128, MROWS / 128), 256>>>(
        p_xemb, W_ih0, b_ih0, b_hh0, p_gatesx, MROWS, GATES, EMBED);

    // 3) layer-0 recurrence (persistent)
    lstm_layer<<<NBLK, 256>>>(W_hh0, p_gatesx, h0, c0, p_hs0, hT, cT);

    // 4) layer-1 input projection
    gemm_abT<<<dim3(GATES / 128, MROWS / 128), 256>>>(
        p_hs0, W_ih1, b_ih1, b_hh1, p_gatesx, MROWS, GATES, HIDDEN);

    // 5) layer-1 recurrence
    lstm_layer<<<NBLK, 256>>>(W_hh1, p_gatesx, h0 + SH, c0 + SH,
                              p_hs1, hT + SH, cT + SH);

    // 6) FC head
    gemm_abT<<<dim3(VOCAB / 128, MROWS / 128), 256>>>(
        p_hs1, fc_W, fc_b, nullptr, logits, MROWS, VOCAB, HIDDEN);
}

// round 3
// speedup vs baseline: 1.0027x; 1.0027x over previous
#include <cuda_runtime.h>
#include <cuda_bf16.h>
#include <cstdint>

// ---------------------------------------------------------------------------
// Problem dims
// ---------------------------------------------------------------------------
#define BATCH   16
#define SEQ     256
#define EMBED   512
#define HIDDEN  1024
#define GATES   (4 * HIDDEN)        // 4096
#define VOCAB   32000
#define MROWS   (BATCH * SEQ)       // 4096
#define NBLK    128                 // persistent LSTM grid size

// ---------------------------------------------------------------------------
// Scratch (device globals; no runtime allocation allowed)
// ---------------------------------------------------------------------------
__device__ float g_xemb  [MROWS * EMBED];     //  8 MB
__device__ float g_gatesx[MROWS * GATES];     // 64 MB: input-projection preacts (+biases)
__device__ float g_hs0   [MROWS * HIDDEN];    // 16 MB
__device__ float g_hs1   [MROWS * HIDDEN];    // 16 MB
__device__ float g_hbuf  [2][BATCH * HIDDEN]; // ping-pong h state
__device__ unsigned g_cnt;                    // grid barrier counter
__device__ volatile unsigned g_gen;           // grid barrier generation (monotonic)

// ---------------------------------------------------------------------------
// Packed f32x2 helpers (FFMA2 — 2x fp32 FMA throughput; PTX-only)
// ---------------------------------------------------------------------------
__device__ __forceinline__ void ffma2(unsigned long long& d,
                                      unsigned long long a,
                                      unsigned long long b) {
    asm("fma.rn.f32x2 %0, %1, %2, %0;" : "+l"(d) : "l"(a), "l"(b));
}
__device__ __forceinline__ unsigned long long pack2(float v) {
    unsigned long long r;
    unsigned int u = __float_as_uint(v);
    asm("mov.b64 %0, {%1, %1};" : "=l"(r) : "r"(u));
    return r;
}
__device__ __forceinline__ float2 unpack2(unsigned long long v) {
    unsigned int lo, hi;
    asm("mov.b64 {%0, %1}, %2;" : "=r"(lo), "=r"(hi) : "l"(v));
    return make_float2(__uint_as_float(lo), __uint_as_float(hi));
}

// ---------------------------------------------------------------------------
// Grid-wide barrier (sense via monotonically increasing generation).
// All NBLK blocks are guaranteed co-resident (NBLK <= SM count, tiny regs).
// ---------------------------------------------------------------------------
__device__ __forceinline__ void grid_bar(unsigned target) {
    __threadfence();
    __syncthreads();
    if (threadIdx.x == 0) {
        unsigned arr = atomicAdd(&g_cnt, 1u);
        if (arr == NBLK - 1) {
            g_cnt = 0;
            __threadfence();
            g_gen = target;            // release
        } else {
            while ((int)(g_gen - target) < 0) {}
            __threadfence();
        }
    }
    __syncthreads();
}

// ---------------------------------------------------------------------------
// Embedding gather (float4 rows)
// ---------------------------------------------------------------------------
__global__ void embed_kernel(const int* __restrict__ x,
                             const float* __restrict__ emb,
                             float* __restrict__ out) {
    int idx = blockIdx.x * 256 + threadIdx.x;   // over float4 units
    int row = idx >> 7;                         // EMBED/4 = 128 per row
    int e4  = idx & 127;
    const float4* src = (const float4*)(emb + ((size_t)x[row] << 9));
    ((float4*)out)[idx] = src[e4];
}

// ---------------------------------------------------------------------------
// fp32 GEMM:  C[M,N] = A[M,K] @ W[N,K]^T + b1 (+ b2)
// 128x128x16 tile, 256 threads, 16(m as 8 f32x2-pairs) x 4(n) micro-tile.
// Requires M%128==0, N%128==0, K%16==0.
// ---------------------------------------------------------------------------
__global__ __launch_bounds__(256, 2)
void gemm_abT(const float* __restrict__ A, const float* __restrict__ W,
              const float* __restrict__ b1, const float* __restrict__ b2,
              float* __restrict__ C, int M, int N, int K) {
    __shared__ float As[16][132];
    __shared__ float Ws[16][132];

    int tid = threadIdx.x;
    int m0 = blockIdx.y << 7;
    int n0 = blockIdx.x << 7;
    int lr = tid >> 2;              // 0..63
    int lc = (tid & 3) << 2;        // 0,4,8,12
    int ty = tid >> 5;              // 0..7  -> 16 rows
    int tx = tid & 31;              // 0..31 -> 4 cols

    unsigned long long acc[4][8];
#pragma unroll
    for (int j = 0; j < 4; j++)
#pragma unroll
        for (int i = 0; i < 8; i++) acc[j][i] = 0ull;

    const float* Ar0 = A + (size_t)(m0 + lr) * K;
    const float* Ar1 = A + (size_t)(m0 + lr + 64) * K;
    const float* Wr0 = W + (size_t)(n0 + lr) * K;
    const float* Wr1 = W + (size_t)(n0 + lr + 64) * K;

    for (int k0 = 0; k0 < K; k0 += 16) {
        float4 a0 = *(const float4*)(Ar0 + k0 + lc);
        float4 a1 = *(const float4*)(Ar1 + k0 + lc);
        float4 w0 = *(const float4*)(Wr0 + k0 + lc);
        float4 w1 = *(const float4*)(Wr1 + k0 + lc);
        __syncthreads();
        As[lc+0][lr] = a0.x; As[lc+1][lr] = a0.y; As[lc+2][lr] = a0.z; As[lc+3][lr] = a0.w;
        As[lc+0][lr+64] = a1.x; As[lc+1][lr+64] = a1.y; As[lc+2][lr+64] = a1.z; As[lc+3][lr+64] = a1.w;
        Ws[lc+0][lr] = w0.x; Ws[lc+1][lr] = w0.y; Ws[lc+2][lr] = w0.z; Ws[lc+3][lr] = w0.w;
        Ws[lc+0][lr+64] = w1.x; Ws[lc+1][lr+64] = w1.y; Ws[lc+2][lr+64] = w1.z; Ws[lc+3][lr+64] = w1.w;
        __syncthreads();

#pragma unroll
        for (int kk = 0; kk < 16; kk++) {
            ulonglong2 ap01 = *(const ulonglong2*)&As[kk][ty*16 + 0];
            ulonglong2 ap23 = *(const ulonglong2*)&As[kk][ty*16 + 4];
            ulonglong2 ap45 = *(const ulonglong2*)&As[kk][ty*16 + 8];
            ulonglong2 ap67 = *(const ulonglong2*)&As[kk][ty*16 + 12];
            float4 wv = *(const float4*)&Ws[kk][tx*4];
            unsigned long long wp0 = pack2(wv.x), wp1 = pack2(wv.y);
            unsigned long long wp2 = pack2(wv.z), wp3 = pack2(wv.w);
            unsigned long long ap[8] = {ap01.x, ap01.y, ap23.x, ap23.y,
                                        ap45.x, ap45.y, ap67.x, ap67.y};
#pragma unroll
            for (int i = 0; i < 8; i++) {
                ffma2(acc[0][i], wp0, ap[i]);
                ffma2(acc[1][i], wp1, ap[i]);
                ffma2(acc[2][i], wp2, ap[i]);
                ffma2(acc[3][i], wp3, ap[i]);
            }
        }
    }

    int n = n0 + (tx << 2);
    float4 bv = *(const float4*)(b1 + n);
    if (b2) {
        float4 t2 = *(const float4*)(b2 + n);
        bv.x += t2.x; bv.y += t2.y; bv.z += t2.z; bv.w += t2.w;
    }
#pragma unroll
    for (int i = 0; i < 8; i++) {
        float2 c0f = unpack2(acc[0][i]);
        float2 c1f = unpack2(acc[1][i]);
        float2 c2f = unpack2(acc[2][i]);
        float2 c3f = unpack2(acc[3][i]);
        int r0 = m0 + ty*16 + 2*i;
        float4 o0 = make_float4(c0f.x + bv.x, c1f.x + bv.y, c2f.x + bv.z, c3f.x + bv.w);
        float4 o1 = make_float4(c0f.y + bv.x, c1f.y + bv.y, c2f.y + bv.z, c3f.y + bv.w);
        *(float4*)(C + (size_t)r0 * N + n) = o0;
        *(float4*)(C + (size_t)(r0 + 1) * N + n) = o1;
    }
}

// ---------------------------------------------------------------------------
// Persistent LSTM layer: 128 blocks x 256 threads, whole sequence in one
// launch. Each block owns 8 hidden columns (x4 gates = 32 W_hh rows); each
// thread = 1 row x 1 batch-pair. h ping-pongs in global (read via __ldcg:
// L1 is not coherent across SMs); c lives in SMEM for the whole layer.
// One grid barrier per timestep.
// ---------------------------------------------------------------------------
__global__ __launch_bounds__(256)
void lstm_layer(const float* __restrict__ Whh,
                const float* __restrict__ gatesx,
                const float* __restrict__ h0l, const float* __restrict__ c0l,
                float* __restrict__ hs,
                float* __restrict__ hT, float* __restrict__ cT) {
    __shared__ float h_sm[512][18];
    __shared__ float gate_sm[32][17];
    __shared__ float c_sm[128];
    __shared__ unsigned base_sh;

    int tid = threadIdx.x;
    int bid = blockIdx.x;

    if (tid == 0) base_sh = g_gen;   // stable: only changes after all blocks arrive
    __syncthreads();
    unsigned tgt = base_sh;

    // init state
    if (tid < 128) {
        g_hbuf[0][bid * 128 + tid] = h0l[bid * 128 + tid];
        int b = tid >> 3, cc = tid & 7;
        c_sm[tid] = c0l[b * HIDDEN + bid * 8 + cc];
    }
    grid_bar(++tgt);

    int lrow = tid >> 3;             // 0..31
    int pr2  = (tid & 7) << 1;       // batch-pair offset
    int q    = lrow >> 3;            // gate index 0..3
    int col  = bid * 8 + (lrow & 7); // hidden column
    const float* wr_base = Whh + (size_t)(q * HIDDEN + col) * HIDDEN;

    for (int t = 0; t < SEQ; t++) {
        const float* hin  = g_hbuf[t & 1];
        float*       hout = g_hbuf[(t + 1) & 1];
        unsigned long long acc = 0ull;

#pragma unroll
        for (int kc = 0; kc < 2; kc++) {
            __syncthreads();
            // load h chunk [512 k x 16 b] transposed into SMEM (L2-fresh)
            for (int i = tid; i < 2048; i += 256) {
                int b  = i >> 7;
                int k4 = (i & 127) << 2;
                float4 v = __ldcg((const float4*)(hin + b * HIDDEN + kc * 512 + k4));
                h_sm[k4 + 0][b] = v.x; h_sm[k4 + 1][b] = v.y;
                h_sm[k4 + 2][b] = v.z; h_sm[k4 + 3][b] = v.w;
            }
            __syncthreads();
            const float* wr = wr_base + kc * 512;
#pragma unroll 4
            for (int k = 0; k < 512; k += 4) {
                float4 w = *(const float4*)(wr + k);
                ffma2(acc, pack2(w.x), *(const unsigned long long*)&h_sm[k + 0][pr2]);
                ffma2(acc, pack2(w.y), *(const unsigned long long*)&h_sm[k + 1][pr2]);
                ffma2(acc, pack2(w.z), *(const unsigned long long*)&h_sm[k + 2][pr2]);
                ffma2(acc, pack2(w.w), *(const unsigned long long*)&h_sm[k + 3][pr2]);
            }
        }

        float2 u = unpack2(acc);
        gate_sm[lrow][pr2]     = u.x;
        gate_sm[lrow][pr2 + 1] = u.y;
        __syncthreads();

        if (tid < 128) {
            int b = tid >> 3, cc = tid & 7;
            int colp = bid * 8 + cc;
            size_t gb = (size_t)(b * SEQ + t) * GATES;
            float gi = gate_sm[cc][b]      + gatesx[gb + colp];
            float gf = gate_sm[8 + cc][b]  + gatesx[gb + 1024 + colp];
            float gg = gate_sm[16 + cc][b] + gatesx[gb + 2048 + colp];
            float go = gate_sm[24 + cc][b] + gatesx[gb + 3072 + colp];
            float si = 1.f / (1.f + expf(-gi));
            float sf = 1.f / (1.f + expf(-gf));
            float tg = tanhf(gg);
            float so = 1.f / (1.f + expf(-go));
            float cn = sf * c_sm[tid] + si * tg;
            c_sm[tid] = cn;
            float hn = so * tanhf(cn);
            hout[b * HIDDEN + colp] = hn;
            hs[(size_t)(b * SEQ + t) * HIDDEN + colp] = hn;
        }
        grid_bar(++tgt);
    }

    // final state writeout (SEQ even -> final h in buffer 0)
    if (tid < 128) {
        hT[bid * 128 + tid] = __ldcg(&g_hbuf[0][bid * 128 + tid]);
        int b = tid >> 3;
        cT[b * HIDDEN + bid * 8 + (tid & 7)] = c_sm[tid];
    }
}

// ---------------------------------------------------------------------------
// Launch: 6 graph nodes total (keeps graph upload device-alloc at zero)
// ---------------------------------------------------------------------------
extern "C" void kernel_launch(void* const* d_in, const int* in_sizes, int n_in,
                              void* d_out, int out_size) {
    const int*   x     = (const int*)  d_in[0];
    const float* h0    = (const float*)d_in[1];
    const float* c0    = (const float*)d_in[2];
    const float* emb   = (const float*)d_in[3];
    const float* W_ih0 = (const float*)d_in[4];
    const float* W_hh0 = (const float*)d_in[5];
    const float* b_ih0 = (const float*)d_in[6];
    const float* b_hh0 = (const float*)d_in[7];
    const float* W_ih1 = (const float*)d_in[8];
    const float* W_hh1 = (const float*)d_in[9];
    const float* b_ih1 = (const float*)d_in[10];
    const float* b_hh1 = (const float*)d_in[11];
    const float* fc_W  = (const float*)d_in[12];
    const float* fc_b  = (const float*)d_in[13];

    float* out    = (float*)d_out;
    float* logits = out;
    float* hT     = out + (size_t)MROWS * VOCAB;
    float* cT     = hT + 2 * BATCH * HIDDEN;

    float *p_xemb, *p_gatesx, *p_hs0, *p_hs1;
    cudaGetSymbolAddress((void**)&p_xemb,   g_xemb);
    cudaGetSymbolAddress((void**)&p_gatesx, g_gatesx);
    cudaGetSymbolAddress((void**)&p_hs0,    g_hs0);
    cudaGetSymbolAddress((void**)&p_hs1,    g_hs1);

    const int SH = BATCH * HIDDEN;

    // 1) embedding
    embed_kernel<<<(MROWS * (EMBED / 4)) / 256, 256>>>(x, emb, p_xemb);

    // 2) layer-0 input projection (both biases folded in)
    gemm_abT<<<dim3(GATES / 128, MROWS / 128), 256>>>(
        p_xemb, W_ih0, b_ih0, b_hh0, p_gatesx, MROWS, GATES, EMBED);

    // 3) layer-0 recurrence (persistent)
    lstm_layer<<<NBLK, 256>>>(W_hh0, p_gatesx, h0, c0, p_hs0, hT, cT);

    // 4) layer-1 input projection
    gemm_abT<<<dim3(GATES / 128, MROWS / 128), 256>>>(
        p_hs0, W_ih1, b_ih1, b_hh1, p_gatesx, MROWS, GATES, HIDDEN);

    // 5) layer-1 recurrence
    lstm_layer<<<NBLK, 256>>>(W_hh1, p_gatesx, h0 + SH, c0 + SH,
                              p_hs1, hT + SH, cT + SH);

    // 6) FC head
    gemm_abT<<<dim3(VOCAB / 128, MROWS / 128), 256>>>(
        p_hs1, fc_W, fc_b, nullptr, logits, MROWS, VOCAB, HIDDEN);
}